// round 1
// baseline (speedup 1.0000x reference)
#include <cuda_runtime.h>

// Problem constants
#define NB   64
#define CIN  64
#define HH   128
#define WW   128
#define COUT 128
#define OH   126   // conv output rows/cols (VALID 3x3)
#define CO_TILE 32
#define ROWS 4          // conv rows per block (= 2 pooled rows)
#define CK   8          // cin per chunk
#define ROW_TILES 32    // ceil(126/4)
#define COG  (COUT/CO_TILE)   // 4

// Deterministic two-stage reduction scratch (written fully every launch)
__device__ float g_partial[NB * ROW_TILES * COG];

__global__ __launch_bounds__(256) void conv_fused_kernel(
    const float* __restrict__ x, const float* __restrict__ Wt,
    const float* __restrict__ bias)
{
    __shared__ float xs[CK][6][132];        // 6 input rows (4 out rows + 2 halo), pad cols 128..131
    __shared__ float ws[CO_TILE][CK][9];
    __shared__ float red[256];

    const int rt   = blockIdx.x;
    const int cog  = blockIdx.y;
    const int n    = blockIdx.z;
    const int r0   = rt * ROWS;
    const int tx   = threadIdx.x;
    const int co_t = tx >> 5;      // 0..7  (constant per warp -> ws loads broadcast)
    const int lane = tx & 31;

    float acc[4][4][4];
    #pragma unroll
    for (int o = 0; o < 4; o++)
        #pragma unroll
        for (int r = 0; r < ROWS; r++)
            #pragma unroll
            for (int g = 0; g < 4; g++) acc[o][r][g] = 0.f;

    const float* xn = x + (size_t)n * CIN * HH * WW;

    // Zero pad columns once (float4 loads below only touch cols 0..127)
    if (tx < 192) {
        int ci = tx / 24; int rr = (tx % 24) >> 2; int c = 128 + (tx & 3);
        xs[ci][rr][c] = 0.f;
    }

    for (int ck = 0; ck < CIN / CK; ck++) {
        __syncthreads();
        // Load x tile: 8 cin x 6 rows x 128 cols, float4 vectorized
        #pragma unroll
        for (int i = 0; i < 6; i++) {
            int idx = tx + 256 * i;          // 0..1535
            int ci  = idx / 192;
            int rem = idx - ci * 192;
            int row = rem >> 5;
            int v   = (rem & 31) << 2;
            int grow = r0 + row;
            float4 val = make_float4(0.f, 0.f, 0.f, 0.f);
            if (grow < HH)
                val = *(const float4*)(xn + ((size_t)(ck * CK + ci) * HH + grow) * WW + v);
            *(float4*)&xs[ci][row][v] = val;
        }
        // Load W tile: 32 co x 8 cin x 9
        #pragma unroll
        for (int i = 0; i < 9; i++) {
            int idx = tx + 256 * i;          // 0..2303
            int co  = idx / 72;
            int rem = idx - co * 72;
            int ci  = rem / 9;
            int k   = rem - ci * 9;
            ws[co][ci][k] = Wt[((size_t)(cog * CO_TILE + co) * CIN + (ck * CK + ci)) * 9 + k];
        }
        __syncthreads();

        #pragma unroll 1
        for (int ci = 0; ci < CK; ci++) {
            float wr[4][3][3];
            #pragma unroll
            for (int o = 0; o < 4; o++)
                #pragma unroll
                for (int kh = 0; kh < 3; kh++)
                    #pragma unroll
                    for (int kw = 0; kw < 3; kw++)
                        wr[o][kh][kw] = ws[co_t + 8 * o][ci][kh * 3 + kw];

            #pragma unroll
            for (int row = 0; row < 6; row++) {
                #pragma unroll
                for (int g = 0; g < 4; g++) {
                    const int b = lane + 32 * g;
                    const float x0 = xs[ci][row][b];
                    const float x1 = xs[ci][row][b + 1];
                    const float x2 = xs[ci][row][b + 2];
                    #pragma unroll
                    for (int kh = 0; kh < 3; kh++) {
                        const int r = row - kh;
                        if (r >= 0 && r < ROWS) {
                            #pragma unroll
                            for (int o = 0; o < 4; o++) {
                                float a = acc[o][r][g];
                                a = fmaf(x0, wr[o][kh][0], a);
                                a = fmaf(x1, wr[o][kh][1], a);
                                a = fmaf(x2, wr[o][kh][2], a);
                                acc[o][r][g] = a;
                            }
                        }
                    }
                }
            }
        }
    }

    // Epilogue: bias + 2x2 mean pool + sigmoid + partial sum
    float lsum = 0.f;
    #pragma unroll
    for (int o = 0; o < 4; o++) {
        const float bb = bias[cog * CO_TILE + co_t + 8 * o];
        #pragma unroll
        for (int p = 0; p < 2; p++) {
            const bool rvalid = (r0 + 2 * p + 1) < OH;
            #pragma unroll
            for (int g = 0; g < 4; g++) {
                float rs = acc[o][2 * p][g] + acc[o][2 * p + 1][g];
                float pr = rs + __shfl_down_sync(0xffffffffu, rs, 1);
                const int b = lane + 32 * g;
                if (rvalid && ((lane & 1) == 0) && b <= 124) {
                    float v = pr * 0.25f + bb;
                    lsum += 1.f / (1.f + __expf(-v));
                }
            }
        }
    }
    red[tx] = lsum;
    __syncthreads();
    #pragma unroll
    for (int s = 128; s > 0; s >>= 1) {
        if (tx < s) red[tx] += red[tx + s];
        __syncthreads();
    }
    if (tx == 0) g_partial[(n * ROW_TILES + rt) * COG + cog] = red[0];
}

__global__ void final_reduce_kernel(float* __restrict__ out)
{
    __shared__ float sm[128];
    const int n = blockIdx.x;
    const int t = threadIdx.x;               // 128 threads = ROW_TILES*COG partials
    sm[t] = g_partial[n * (ROW_TILES * COG) + t];
    __syncthreads();
    #pragma unroll
    for (int s = 64; s > 0; s >>= 1) {
        if (t < s) sm[t] += sm[t + s];
        __syncthreads();
    }
    if (t == 0) out[n] = sm[0];
}

extern "C" void kernel_launch(void* const* d_in, const int* in_sizes, int n_in,
                              void* d_out, int out_size)
{
    const float* x  = (const float*)d_in[0];   // (64,64,128,128)
    const float* Wt = (const float*)d_in[1];   // (128,64,3,3)
    const float* b  = (const float*)d_in[2];   // (128,)
    float* out = (float*)d_out;                // (64,)

    dim3 grid(ROW_TILES, COG, NB);
    conv_fused_kernel<<<grid, 256>>>(x, Wt, b);
    final_reduce_kernel<<<NB, 128>>>(out);
}

// round 7
// speedup vs baseline: 5.1679x; 5.1679x over previous
#include <cuda_runtime.h>
#include <cuda_bf16.h>
#include <cstdint>

// ---------------------------------------------------------------------------
// conv3x3(VALID)+bias+2x2meanpool+sigmoid+per-batch-sum via mma.sync bf16
// (tcgen05 unavailable: harness compiles PTX for plain sm_103, no 'a' feature)
// GEMM view per (image, col-half, pooled-row-pair):
//   D[co][n] = sum_{k=s*64+ci} Wa[co][k] * x[ci][r0+dr+kh][c0+col+kw]
//   n = col*2 + dr  (col 0..63 local, dr = conv row 0/1, dr bound via B row slot)
// Audited: fragment maps, ring-slot reuse, bank patterns, edge masks, bounds.
// ---------------------------------------------------------------------------

#define NBATCH 64
#define CIN    64
#define KTOT   576
#define ASTRIDE 1168            // 584 bf16 per co (576 + 8 pad) == 4 words mod 32
#define A_BYTES (128*ASTRIDE)   // 149504
#define BSLOT  9536             // row-slot bytes (66*144 used) == 16 words mod 32
#define B_OFF  A_BYTES
#define B_BYTES (4*BSLOT)       // 38144
#define RED_OFF (B_OFF + B_BYTES)
#define SMEM_REQ (RED_OFF + 64) // 187712 <= 227KB opt-in

__device__ __align__(16) unsigned char g_xt[(size_t)64*128*128*128]; // [n][row][col][64ci bf16]
__device__ __align__(16) unsigned char g_Wa[A_BYTES];
__device__ float g_partial[NBATCH * 2];

// ---- prep: W f32 -> bf16 [co][k = s*64+ci], stride 584 bf16 ----
__global__ void prep_w_kernel(const float* __restrict__ W) {
    int idx = blockIdx.x * 256 + threadIdx.x;    // 128*576 = 73728
    if (idx >= 128 * KTOT) return;
    int co = idx / KTOT, k = idx % KTOT;
    int s = k >> 6, ci = k & 63;
    ((__nv_bfloat16*)g_Wa)[co * 584 + k] = __float2bfloat16(W[(co * 64 + ci) * 9 + s]);
}

// ---- transpose: x f32 [n][ci][row][col] -> g_xt bf16 [n][row][col][ci] ----
__global__ __launch_bounds__(256) void transpose_x_kernel(const float* __restrict__ x) {
    __shared__ uint32_t sm[128][33];
    const int row = blockIdx.x, n = blockIdx.y;
    const int tx = threadIdx.x, w = tx >> 5, lane = tx & 31;
    const float* xb = x + (size_t)n * CIN * 128 * 128 + (size_t)row * 128;
    #pragma unroll
    for (int it = 0; it < 16; it++) {
        int task = w * 16 + it;          // 0..127 = 32 cipairs x 4 colgroups
        int cp = task & 31, cg = task >> 5;
        int col = cg * 32 + lane;
        float f0 = xb[(size_t)(2 * cp) * 16384 + col];
        float f1 = xb[(size_t)(2 * cp + 1) * 16384 + col];
        __nv_bfloat162 p = __floats2bfloat162_rn(f0, f1);  // low = even ci
        sm[col][cp] = *(uint32_t*)&p;
    }
    __syncthreads();
    uint32_t* out = (uint32_t*)g_xt + ((size_t)(n * 128 + row) * 128) * 32;
    #pragma unroll
    for (int it = 0; it < 16; it++) {
        int col = w * 16 + it;
        out[col * 32 + lane] = sm[col][lane];
    }
}

// ---- mma.sync wrapper ----
__device__ __forceinline__ void mma16816(float* c, uint32_t a0, uint32_t a1,
                                         uint32_t a2, uint32_t a3,
                                         uint32_t b0, uint32_t b1) {
    asm volatile(
        "mma.sync.aligned.m16n8k16.row.col.f32.bf16.bf16.f32 "
        "{%0,%1,%2,%3},{%4,%5,%6,%7},{%8,%9},{%0,%1,%2,%3};"
        : "+f"(c[0]), "+f"(c[1]), "+f"(c[2]), "+f"(c[3])
        : "r"(a0), "r"(a1), "r"(a2), "r"(a3), "r"(b0), "r"(b1));
}

// ---- main fused kernel: grid (2 col-halves, 64 images), 256 threads -------
__global__ __launch_bounds__(256, 1) void conv_mma_kernel(
    const float* __restrict__ bias)
{
    extern __shared__ unsigned char smem[];
    const int ch = blockIdx.x, n = blockIdx.y;
    const int c0 = ch * 64;
    const int tx = threadIdx.x, wid = tx >> 5, lane = tx & 31;
    const int wm = wid & 1, wn = wid >> 1;         // 2 M-warps x 4 N-warps
    const int g  = lane >> 2, qd = lane & 3;

    // A: weights to smem (contiguous copy, layout identical)
    {
        const float4* src = (const float4*)g_Wa;
        float4* dst = (float4*)smem;
        for (int i = tx; i < A_BYTES / 16; i += 256) dst[i] = src[i];
    }

    float bias_lo[4], bias_hi[4];
    #pragma unroll
    for (int mt = 0; mt < 4; mt++) {
        int m = wm * 64 + mt * 16 + g;
        bias_lo[mt] = __ldg(&bias[m]);
        bias_hi[mt] = __ldg(&bias[m + 8]);
    }

    // per-lane fragment base offsets (bytes)
    const uint32_t aBase = (uint32_t)(wm * 64 + g) * ASTRIDE + qd * 4;
    const uint32_t bColPart = (uint32_t)(wn * 16 + (g >> 1)) * 144 + qd * 4;
    const int drl = g & 1;

    const uint4* xt4 = (const uint4*)g_xt;
    unsigned char* smB = smem + B_OFF;
    float lsum = 0.f;

    for (int pr = 0; pr < 63; pr++) {
        const int r0 = 2 * pr;
        __syncthreads();                       // prev compute done before slot reuse
        // ---- fill B row slots (pr==0: rows 0..3, else new rows r0+2, r0+3)
        {
            const int rstart = (pr == 0) ? 0 : r0 + 2;
            const int total = (pr == 0) ? 4 * 528 : 2 * 528;
            for (int e = tx; e < total; e += 256) {
                int r = rstart + e / 528;
                int rem = e % 528;
                int colx = rem >> 3, j = rem & 7;
                int gcol = c0 + colx;
                uint4 v = make_uint4(0u, 0u, 0u, 0u);
                if (gcol < 128)
                    v = xt4[(((size_t)(n * 128 + r) * 128 + gcol) << 3) + j];
                *(uint4*)(smB + (r & 3) * BSLOT + colx * 144 + j * 16) = v;
            }
        }
        __syncthreads();

        float acc[4][4][4];
        #pragma unroll
        for (int mt = 0; mt < 4; mt++)
            #pragma unroll
            for (int t = 0; t < 4; t++)
                #pragma unroll
                for (int i = 0; i < 4; i++) acc[mt][t][i] = 0.f;

        // ---- K loop: 9 shifts x 4 k16 steps
        #pragma unroll 1
        for (int s = 0; s < 9; s++) {
            const int kh = s / 3, kw = s % 3;
            const uint32_t bS = (uint32_t)((r0 + drl + kh) & 3) * BSLOT
                              + (uint32_t)kw * 144 + bColPart;
            const uint32_t aS = aBase + (uint32_t)s * 128;
            #pragma unroll
            for (int k16 = 0; k16 < 4; k16++) {
                const uint32_t ak = aS + k16 * 32;
                const uint32_t bk = bS + k16 * 32;
                uint32_t breg[4][2];
                #pragma unroll
                for (int t = 0; t < 4; t++) {
                    breg[t][0] = *(const uint32_t*)(smB + bk + t * 576);
                    breg[t][1] = *(const uint32_t*)(smB + bk + t * 576 + 16);
                }
                #pragma unroll
                for (int mt = 0; mt < 4; mt++) {
                    const uint32_t am = ak + (uint32_t)(mt * 16) * ASTRIDE;
                    uint32_t a0 = *(const uint32_t*)(smem + am);
                    uint32_t a1 = *(const uint32_t*)(smem + am + 8 * ASTRIDE);
                    uint32_t a2 = *(const uint32_t*)(smem + am + 16);
                    uint32_t a3 = *(const uint32_t*)(smem + am + 8 * ASTRIDE + 16);
                    #pragma unroll
                    for (int t = 0; t < 4; t++)
                        mma16816(acc[mt][t], a0, a1, a2, a3, breg[t][0], breg[t][1]);
                }
            }
        }

        // ---- epilogue: dr pair in-thread, col pair via shfl, sigmoid
        const int keep = ((qd & 1) == 0);
        #pragma unroll
        for (int mt = 0; mt < 4; mt++) {
            #pragma unroll
            for (int t = 0; t < 4; t++) {
                float rs0 = acc[mt][t][0] + acc[mt][t][1];
                float rs1 = acc[mt][t][2] + acc[mt][t][3];
                float p0 = rs0 + __shfl_xor_sync(0xffffffffu, rs0, 1);
                float p1 = rs1 + __shfl_xor_sync(0xffffffffu, rs1, 1);
                bool valid = keep && !(ch && wn == 3 && t == 3 && qd == 2);
                if (valid) {
                    float v0 = p0 * 0.25f + bias_lo[mt];
                    float v1 = p1 * 0.25f + bias_hi[mt];
                    lsum += 1.f / (1.f + __expf(-v0));
                    lsum += 1.f / (1.f + __expf(-v1));
                }
            }
        }
    }

    // ---- block reduce
    #pragma unroll
    for (int s = 16; s > 0; s >>= 1) lsum += __shfl_xor_sync(0xffffffffu, lsum, s);
    float* wred = (float*)(smem + RED_OFF);
    if (lane == 0) wred[wid] = lsum;
    __syncthreads();
    if (tx == 0) {
        float t = 0.f;
        #pragma unroll
        for (int w = 0; w < 8; w++) t += wred[w];
        g_partial[n * 2 + ch] = t;
    }
}

__global__ void final_reduce_kernel(float* __restrict__ out) {
    int t = threadIdx.x;  // 64
    out[t] = g_partial[2 * t] + g_partial[2 * t + 1];
}

extern "C" void kernel_launch(void* const* d_in, const int* in_sizes, int n_in,
                              void* d_out, int out_size)
{
    const float* x  = (const float*)d_in[0];   // (64,64,128,128)
    const float* Wt = (const float*)d_in[1];   // (128,64,3,3)
    const float* b  = (const float*)d_in[2];   // (128,)
    float* out = (float*)d_out;                // (64,)

    cudaFuncSetAttribute(conv_mma_kernel,
                         cudaFuncAttributeMaxDynamicSharedMemorySize, SMEM_REQ);

    prep_w_kernel<<<288, 256>>>(Wt);
    dim3 tg(128, 64);
    transpose_x_kernel<<<tg, 256>>>(x);
    dim3 grid(2, 64);
    conv_mma_kernel<<<grid, 256, SMEM_REQ>>>(b);
    final_reduce_kernel<<<1, 64>>>(out);
}

// round 8
// speedup vs baseline: 8.4449x; 1.6341x over previous
#include <cuda_runtime.h>
#include <cuda_bf16.h>
#include <cstdint>

// ---------------------------------------------------------------------------
// conv3x3+bias+2x2meanpool+sigmoid+sum == stride-2 4x4 conv (W' = summed W /4)
//   pooled[co][pr][pc] = sum_{u,v,ci} W'[co][u,v,ci] * x[ci][2pr+u][2pc+v] + b
// GEMM per (image, co-half, col-half, outer o): M=64 co, N=64 (32 pc x 2 pr),
// K=1024 (16 shifts x 64 ci). mma.sync m16n8k16 bf16, ldmatrix fragments.
// ---------------------------------------------------------------------------

#define ASTR  2064                 // 1032 bf16 per co (1024 + 8 pad); ==4 words mod 32
#define A_SM  (64*ASTR)            // 132096
#define BSLOT 9616                 // ==4 words mod 32; 66 cols x 144B + stagger fits
#define B_OFF A_SM
#define SMEM_REQ (A_SM + 8*BSLOT + 64)   // 209088

__device__ __align__(16) unsigned char g_xt[(size_t)64*128*128*128]; // [n][row][col][64ci bf16]
__device__ __align__(16) unsigned char g_Wp[(size_t)128*ASTR];       // W' bf16 [co][s*64+ci]
__device__ float g_partial[64*4];

// ---- prep: W -> W' (4x4 pooled kernel, incl. 1/4), bf16 ----
__global__ void prep_w_kernel(const float* __restrict__ W) {
    int idx = blockIdx.x * 256 + threadIdx.x;      // 128co*16s*64ci = 131072
    if (idx >= 131072) return;
    int ci = idx & 63, s = (idx >> 6) & 15, co = idx >> 10;
    int u = s >> 2, v = s & 3;
    float acc = 0.f;
    #pragma unroll
    for (int dh = 0; dh < 2; dh++) {
        int kh = u - dh; if (kh < 0 || kh > 2) continue;
        #pragma unroll
        for (int dw = 0; dw < 2; dw++) {
            int kw = v - dw; if (kw < 0 || kw > 2) continue;
            acc += W[(co * 64 + ci) * 9 + kh * 3 + kw];
        }
    }
    ((__nv_bfloat16*)g_Wp)[co * 1032 + s * 64 + ci] = __float2bfloat16(0.25f * acc);
}

// ---- transpose: x f32 [n][ci][row][col] -> g_xt bf16 [n][row][col][ci] ----
__global__ __launch_bounds__(256) void transpose_x_kernel(const float* __restrict__ x) {
    __shared__ uint32_t sm[128][33];
    const int row = blockIdx.x, n = blockIdx.y;
    const int tx = threadIdx.x, w = tx >> 5, lane = tx & 31;
    const float* xb = x + (size_t)n * 64 * 128 * 128 + (size_t)row * 128;
    #pragma unroll
    for (int it = 0; it < 16; it++) {
        int task = w * 16 + it;
        int cp = task & 31, cg = task >> 5;
        int col = cg * 32 + lane;
        float f0 = xb[(size_t)(2 * cp) * 16384 + col];
        float f1 = xb[(size_t)(2 * cp + 1) * 16384 + col];
        __nv_bfloat162 p = __floats2bfloat162_rn(f0, f1);
        sm[col][cp] = *(uint32_t*)&p;
    }
    __syncthreads();
    uint32_t* out = (uint32_t*)g_xt + ((size_t)(n * 128 + row) * 128) * 32;
    #pragma unroll
    for (int it = 0; it < 16; it++) {
        int col = w * 16 + it;
        out[col * 32 + lane] = sm[col][lane];
    }
}

// ---- asm helpers ----
__device__ __forceinline__ uint32_t smem_u32(const void* p) {
    uint32_t a;
    asm("{ .reg .u64 t; cvta.to.shared.u64 t, %1; cvt.u32.u64 %0, t; }" : "=r"(a) : "l"(p));
    return a;
}
#define LDM4(R, addr) \
    asm volatile("ldmatrix.sync.aligned.m8n8.x4.shared.b16 {%0,%1,%2,%3}, [%4];" \
        : "=r"((R)[0]), "=r"((R)[1]), "=r"((R)[2]), "=r"((R)[3]) : "r"(addr))
__device__ __forceinline__ void mma16816(float* c, const uint32_t* a,
                                         uint32_t b0, uint32_t b1) {
    asm volatile(
        "mma.sync.aligned.m16n8k16.row.col.f32.bf16.bf16.f32 "
        "{%0,%1,%2,%3},{%4,%5,%6,%7},{%8,%9},{%0,%1,%2,%3};"
        : "+f"(c[0]), "+f"(c[1]), "+f"(c[2]), "+f"(c[3])
        : "r"(a[0]), "r"(a[1]), "r"(a[2]), "r"(a[3]), "r"(b0), "r"(b1));
}
__device__ __forceinline__ float sigm(float x) { return 1.f / (1.f + __expf(-x)); }

// row base inside B region: 8-slot ring + 16B stagger (breaks ldmatrix
// phase conflicts between row-parity and col-pair bank patterns)
__device__ __forceinline__ uint32_t rowbase(int r) {
    return (uint32_t)(r & 7) * BSLOT + ((r >> 1) & 1) * 16;
}

// ---- main kernel: grid (4 = cohalf*2+colhalf, 64 images), 256 threads ----
__global__ __launch_bounds__(256, 1) void conv_mma2_kernel(const float* __restrict__ bias)
{
    extern __shared__ unsigned char smem[];
    const uint32_t sbase = smem_u32(smem);
    const int bx = blockIdx.x, n = blockIdx.y;
    const int cohalf = bx >> 1, colhalf = bx & 1;
    const int tx = threadIdx.x, wid = tx >> 5, lane = tx & 31;
    const int wm = wid & 1, wn = wid >> 1;          // 2 M-warps x 4 N-warps
    const int g = lane >> 2, qd = lane & 3;

    // A (64 co x 1024 k) to smem
    {
        const float4* src = (const float4*)(g_Wp + (size_t)cohalf * 64 * ASTR);
        float4* dst = (float4*)smem;
        for (int i = tx; i < A_SM / 16; i += 256) dst[i] = src[i];
    }

    float bV[2][2];
    #pragma unroll
    for (int mt = 0; mt < 2; mt++)
        #pragma unroll
        for (int h = 0; h < 2; h++)
            bV[mt][h] = __ldg(&bias[cohalf * 64 + wm * 32 + mt * 16 + h * 8 + g]);

    // pc validity per nt (pc = colhalf*32 + wn*8 + nt*4 + qd; pc 63 invalid)
    bool pcv[2];
    #pragma unroll
    for (int nt = 0; nt < 2; nt++)
        pcv[nt] = !(colhalf == 1 && wn == 3 && nt == 1 && qd == 3);

    // A ldmatrix lane offsets (mats: m0k0, m8k0, m0k8, m8k8)
    const int khA = (lane >> 4) & 1, mhA = (lane >> 3) & 1, frA = lane & 7;
    uint32_t aOff[2];
    #pragma unroll
    for (int mt = 0; mt < 2; mt++)
        aOff[mt] = (uint32_t)(wm * 32 + mt * 16 + mhA * 8 + frA) * ASTR + khA * 16;

    // B ldmatrix lane geometry (mats: nt0k0, nt0k8, nt1k0, nt1k8)
    const int ntB = (lane >> 4) & 1, khB = (lane >> 3) & 1, frB = lane & 7;
    const int nBl = wn * 16 + ntB * 8 + frB;
    const int prlB = nBl & 1;
    const uint32_t bColOff = (uint32_t)(nBl >> 1) * 288 + khB * 16;

    const uint4* xt4 = (const uint4*)g_xt + (size_t)n * 131072;
    const int colbase = colhalf * 64;

    // initial fill: rows 0..5
    for (int e = tx; e < 6 * 528; e += 256) {
        int r = e / 528, rem = e - r * 528;
        int col = rem >> 3, j = rem & 7;
        int gcol = colbase + col;
        uint4 v = make_uint4(0u, 0u, 0u, 0u);
        if (gcol < 128) v = xt4[((size_t)r * 128 + gcol) * 8 + j];
        *(uint4*)(smem + B_OFF + rowbase(r) + col * 144 + j * 16) = v;
    }

    uint4 pv[9];
    // prefetch rows rb..rb+3 into registers
    auto prefetch = [&](int rb) {
        #pragma unroll
        for (int i = 0; i < 9; i++) {
            int e = tx + 256 * i;
            pv[i] = make_uint4(0u, 0u, 0u, 0u);
            if (e < 2112) {
                int r = rb + e / 528, rem = e % 528;
                int col = rem >> 3, j = rem & 7;
                int gcol = colbase + col;
                if (r < 128 && gcol < 128)
                    pv[i] = xt4[((size_t)r * 128 + gcol) * 8 + j];
            }
        }
    };
    auto storepv = [&](int rb) {
        #pragma unroll
        for (int i = 0; i < 9; i++) {
            int e = tx + 256 * i;
            if (e < 2112) {
                int r = rb + e / 528, rem = e % 528;
                int col = rem >> 3, j = rem & 7;
                *(uint4*)(smem + B_OFF + rowbase(r) + col * 144 + j * 16) = pv[i];
            }
        }
    };

    prefetch(6);
    __syncthreads();

    float lsum = 0.f;
    for (int o = 0; o < 32; o++) {
        float acc[2][2][4];
        #pragma unroll
        for (int mt = 0; mt < 2; mt++)
            #pragma unroll
            for (int nt = 0; nt < 2; nt++)
                #pragma unroll
                for (int i = 0; i < 4; i++) acc[mt][nt][i] = 0.f;

        // K loop: 16 shifts (u,v) x 4 ci-chunks
        #pragma unroll 1
        for (int u = 0; u < 4; u++) {
            const int rB = 4 * o + 2 * prlB + u;
            const uint32_t bRow = sbase + B_OFF + rowbase(rB) + bColOff;
            #pragma unroll
            for (int v = 0; v < 4; v++) {
                const uint32_t bS = bRow + v * 144;
                const uint32_t aS = sbase + (uint32_t)((u * 4 + v) * 128);
                #pragma unroll
                for (int kk = 0; kk < 4; kk++) {
                    uint32_t A0[4], A1[4], B0[4];
                    LDM4(A0, aS + aOff[0] + kk * 32);
                    LDM4(A1, aS + aOff[1] + kk * 32);
                    LDM4(B0, bS + kk * 32);
                    mma16816(acc[0][0], A0, B0[0], B0[1]);
                    mma16816(acc[0][1], A0, B0[2], B0[3]);
                    mma16816(acc[1][0], A1, B0[0], B0[1]);
                    mma16816(acc[1][1], A1, B0[2], B0[3]);
                }
            }
        }

        // epilogue: every D element is a pooled output. c0/c2: pr=2o; c1/c3: 2o+1
        const bool pr1v = (o < 31);
        #pragma unroll
        for (int mt = 0; mt < 2; mt++)
            #pragma unroll
            for (int nt = 0; nt < 2; nt++)
                if (pcv[nt]) {
                    lsum += sigm(acc[mt][nt][0] + bV[mt][0]);
                    lsum += sigm(acc[mt][nt][2] + bV[mt][1]);
                    if (pr1v) {
                        lsum += sigm(acc[mt][nt][1] + bV[mt][0]);
                        lsum += sigm(acc[mt][nt][3] + bV[mt][1]);
                    }
                }

        if (o < 31) {
            __syncthreads();                  // all reads of retiring slots done
            storepv(4 * o + 6);               // rows for o+1
            prefetch(4 * o + 10);             // rows for o+2 (latency hidden)
            __syncthreads();
        }
    }

    // block reduce
    #pragma unroll
    for (int s = 16; s > 0; s >>= 1) lsum += __shfl_xor_sync(0xffffffffu, lsum, s);
    __shared__ float wred[8];
    if (lane == 0) wred[wid] = lsum;
    __syncthreads();
    if (tx == 0) {
        float t = 0.f;
        #pragma unroll
        for (int w = 0; w < 8; w++) t += wred[w];
        g_partial[n * 4 + bx] = t;
    }
}

__global__ void final_reduce_kernel(float* __restrict__ out) {
    int t = threadIdx.x;  // 64
    float s = 0.f;
    #pragma unroll
    for (int j = 0; j < 4; j++) s += g_partial[t * 4 + j];
    out[t] = s;
}

extern "C" void kernel_launch(void* const* d_in, const int* in_sizes, int n_in,
                              void* d_out, int out_size)
{
    const float* x  = (const float*)d_in[0];   // (64,64,128,128)
    const float* Wt = (const float*)d_in[1];   // (128,64,3,3)
    const float* b  = (const float*)d_in[2];   // (128,)
    float* out = (float*)d_out;                // (64,)

    cudaFuncSetAttribute(conv_mma2_kernel,
                         cudaFuncAttributeMaxDynamicSharedMemorySize, SMEM_REQ);

    prep_w_kernel<<<512, 256>>>(Wt);
    dim3 tg(128, 64);
    transpose_x_kernel<<<tg, 256>>>(x);
    dim3 grid(4, 64);
    conv_mma2_kernel<<<grid, 256, SMEM_REQ>>>(b);
    final_reduce_kernel<<<1, 64>>>(out);
}